// round 13
// baseline (speedup 1.0000x reference)
#include <cuda_runtime.h>
#include <cuda_fp16.h>

// Problem constants
#define BB    4
#define NR    2
#define NREF  4
#define HH    320
#define WW    320
#define NPIX  (HH*WW)
#define NCAM  (BB*NR)
#define NIMG  (BB*NREF)
#define TPB   256
#define PIX_PER_BLK (TPB*2)
#define BLK_PER_IMG (NPIX/PIX_PER_BLK)   // 200

// Zero-padded pair-packed fp16 RGBX reference images.
// Logical texel coords x in [-2, W], y in [-2, H+1]; texels outside
// [0,W-1]x[0,H-1] are zero. Entry (r, j) holds pair (texel[y][x], texel[y][x+1])
// with y = r-2, x = j-2. One LDG.128 fetches a bilinear corner row, and all
// out-of-range corners read zeros -> no masks or fixups needed in the sampler.
#define WP (WW + 3)              // 323 pair columns (x = -2 .. W)
#define HP (HH + 4)              // 324 rows         (y = -2 .. H+1)
#define IMG_STRIDE (WP * HP)     // 104652
__device__ uint4 g_pair[NIMG * IMG_STRIDE];   // ~26.8 MB

__device__ __forceinline__ void inv3(const float* m, float* o) {
    float a=m[0],b=m[1],c=m[2],d=m[3],e=m[4],f=m[5],g=m[6],h=m[7],i=m[8];
    float A  =  (e*i - f*h);
    float Bm = -(d*i - f*g);
    float C  =  (d*h - e*g);
    float det = a*A + b*Bm + c*C;
    float id = 1.0f/det;
    o[0]=A*id;              o[1]=-(b*i - c*h)*id;   o[2]= (b*f - c*e)*id;
    o[3]=Bm*id;             o[4]= (a*i - c*g)*id;   o[5]=-(a*f - c*d)*id;
    o[6]=C*id;              o[7]=-(a*h - b*g)*id;   o[8]= (a*e - b*d)*id;
}

__device__ __forceinline__ unsigned int ph2(float a, float b) {
    __half2 h = __floats2half2_rn(a, b);
    return *reinterpret_cast<const unsigned int*>(&h);
}
__device__ __forceinline__ float2 h2f2(unsigned int u) {
    return __half22float2(*reinterpret_cast<const __half2*>(&u));
}
__device__ __forceinline__ float h2lo(unsigned int u) {
    return __low2float(*reinterpret_cast<const __half2*>(&u));
}

// Planar CHW fp32 -> zero-padded pair-packed fp16 RGBX
// grid = (ceil(IMG_STRIDE/TPB), NIMG)
__global__ __launch_bounds__(TPB)
void repack_kernel(const float* __restrict__ src) {
    const int e = blockIdx.x * TPB + threadIdx.x;
    if (e >= IMG_STRIDE) return;
    const int img = blockIdx.y;
    const int r = e / WP;
    const int j = e - r * WP;
    const int y = r - 2;
    const int x = j - 2;

    float r0 = 0.f, g0 = 0.f, b0 = 0.f;
    float r1 = 0.f, g1 = 0.f, b1 = 0.f;
    if ((unsigned)y < (unsigned)HH) {
        const float* s = src + img * 3 * NPIX + y * WW;
        if ((unsigned)x < (unsigned)WW) {
            r0 = __ldg(s + x);
            g0 = __ldg(s + NPIX + x);
            b0 = __ldg(s + 2*NPIX + x);
        }
        const int x1 = x + 1;
        if ((unsigned)x1 < (unsigned)WW) {
            r1 = __ldg(s + x1);
            g1 = __ldg(s + NPIX + x1);
            b1 = __ldg(s + 2*NPIX + x1);
        }
    }
    uint4 q;
    q.x = ph2(r0, g0);
    q.y = ph2(b0, 0.0f);
    q.z = ph2(r1, g1);
    q.w = ph2(b1, 0.0f);
    g_pair[img * IMG_STRIDE + e] = q;
}

__global__ __launch_bounds__(TPB, 5)
void tex_kernel(const float* __restrict__ depth,
                const float* __restrict__ background,
                const float* __restrict__ camK,
                const float* __restrict__ camW,
                const float* __restrict__ Kref,
                const float* __restrict__ Wref,
                float* __restrict__ out)
{
    const int cam = blockIdx.x / BLK_PER_IMG;            // b*NR + r
    const int pp  = (blockIdx.x % BLK_PER_IMG)*PIX_PER_BLK + threadIdx.x*2;
    const int b   = cam / NR;
    const int y   = pp / WW;
    const int x   = pp % WW;     // even; pixel pair is (x, x+1), same row

    // ---- Per-block fused camera constants in shared ----
    __shared__ float sP[NREF][9];
    __shared__ float sPt[NREF][3];
    __shared__ float sA[9];
    __shared__ float sBv[3];

    if (threadIdx.x < NREF) {
        const int v = threadIdx.x;
        float K[9], R[9], t[3];
        const float* kp = Kref + (b*NREF + v)*9;
        #pragma unroll
        for (int j = 0; j < 9; j++) K[j] = __ldg(kp + j);
        const float* w = Wref + (b*NREF + v)*12;
        #pragma unroll
        for (int r = 0; r < 3; r++) {
            R[r*3+0] = __ldg(w + r*4 + 0);
            R[r*3+1] = __ldg(w + r*4 + 1);
            R[r*3+2] = __ldg(w + r*4 + 2);
            t[r]     = __ldg(w + r*4 + 3);
        }
        #pragma unroll
        for (int r = 0; r < 3; r++) {
            #pragma unroll
            for (int c = 0; c < 3; c++)
                sP[v][r*3+c] = K[r*3+0]*R[0*3+c] + K[r*3+1]*R[1*3+c] + K[r*3+2]*R[2*3+c];
            sPt[v][r] = K[r*3+0]*t[0] + K[r*3+1]*t[1] + K[r*3+2]*t[2];
        }
    } else if (threadIdx.x == NREF) {
        float K[9], R[9], t[3], iK[9], iR[9];
        const float* kp = camK + cam*9;
        #pragma unroll
        for (int j = 0; j < 9; j++) K[j] = __ldg(kp + j);
        const float* w = camW + cam*12;
        #pragma unroll
        for (int r = 0; r < 3; r++) {
            R[r*3+0] = __ldg(w + r*4 + 0);
            R[r*3+1] = __ldg(w + r*4 + 1);
            R[r*3+2] = __ldg(w + r*4 + 2);
            t[r]     = __ldg(w + r*4 + 3);
        }
        inv3(K, iK);
        inv3(R, iR);
        #pragma unroll
        for (int r = 0; r < 3; r++) {
            #pragma unroll
            for (int c = 0; c < 3; c++)
                sA[r*3+c] = iR[r*3+0]*iK[0*3+c] + iR[r*3+1]*iK[1*3+c] + iR[r*3+2]*iK[2*3+c];
            sBv[r] = iR[r*3+0]*t[0] + iR[r*3+1]*t[1] + iR[r*3+2]*t[2];
        }
    }
    __syncthreads();

    const int out_base = cam*3*NPIX + pp;

    // Depth pair (8B-aligned: pp even)
    const float2 d2 = *reinterpret_cast<const float2*>(depth + cam*NPIX + pp);
    const bool val0 = d2.x > 0.0f;
    const bool val1 = d2.y > 0.0f;
    const float yf = (float)y;

    // Backproject both pixels (p3d = nd*(A@(x,y,1)) - Bv)
    float p3[2][3];
    #pragma unroll
    for (int k = 0; k < 2; k++) {
        if ((k == 0) ? val0 : val1) {
            const float d  = (k == 0) ? d2.x : d2.y;
            const float xf = (float)(x + k);
            const float nd = -d;
            p3[k][0] = nd*(sA[0]*xf + sA[1]*yf + sA[2]) - sBv[0];
            p3[k][1] = nd*(sA[3]*xf + sA[4]*yf + sA[5]) - sBv[1];
            p3[k][2] = nd*(sA[6]*xf + sA[7]*yf + sA[8]) - sBv[2];
        }
    }

    float acc[2][3] = {{0.f,0.f,0.f},{0.f,0.f,0.f}};

    if (val0 || val1) {
        #pragma unroll
        for (int v = 0; v < NREF; v++) {
            // Matrix in registers once per ref, shared by both pixels
            const float P0=sP[v][0], P1=sP[v][1], P2=sP[v][2];
            const float P3=sP[v][3], P4=sP[v][4], P5=sP[v][5];
            const float P6=sP[v][6], P7=sP[v][7], P8=sP[v][8];
            const float t0=sPt[v][0], t1=sPt[v][1], t2=sPt[v][2];
            const uint4* __restrict__ pimg = g_pair + (b*NREF + v) * IMG_STRIDE;

            #pragma unroll
            for (int k = 0; k < 2; k++) {
                if (!((k == 0) ? val0 : val1)) continue;
                const float px3 = p3[k][0], py3 = p3[k][1], pz3 = p3[k][2];
                const float qx = P0*px3 + P1*py3 + P2*pz3 + t0;
                const float qy = P3*px3 + P4*py3 + P5*pz3 + t1;
                const float qz = P6*px3 + P7*py3 + P8*pz3 + t2;
                const float iz = __fdividef(1.0f, qz);
                // Clamp into padded domain: everything outside lands on zero
                // texels (fmaxf/fminf also swallow NaN -> -2 -> zero region).
                const float px = fminf(fmaxf(qx * iz, -2.0f), (float)WW);
                const float py = fminf(fmaxf(qy * iz, -2.0f), (float)HH);

                const float x0 = floorf(px);
                const float y0 = floorf(py);
                const float wx = px - x0;
                const float wy = py - y0;
                const int ix = __float2int_rz(x0);   // [-2, W], exact
                const int iy = __float2int_rz(y0);   // [-2, H], exact

                const int idx = iy*WP + ix + (2*WP + 2);
                const uint4 top = __ldg(pimg + idx);
                const uint4 bot = __ldg(pimg + idx + WP);

                const float wx1 = wx,        wx0 = 1.0f - wx;
                const float wy1 = wy,        wy0 = 1.0f - wy;
                const float w00 = wx0*wy0, w01 = wx1*wy0;
                const float w10 = wx0*wy1, w11 = wx1*wy1;

                const float2 rg00 = h2f2(top.x); const float b00 = h2lo(top.y);
                const float2 rg01 = h2f2(top.z); const float b01 = h2lo(top.w);
                const float2 rg10 = h2f2(bot.x); const float b10 = h2lo(bot.y);
                const float2 rg11 = h2f2(bot.z); const float b11 = h2lo(bot.w);

                acc[k][0] += w00*rg00.x + w01*rg01.x + w10*rg10.x + w11*rg11.x;
                acc[k][1] += w00*rg00.y + w01*rg01.y + w10*rg10.y + w11*rg11.y;
                acc[k][2] += w00*b00    + w01*b01    + w10*b10    + w11*b11;
            }
        }
    }

    // Epilogue: background loads only where needed (predicated), then
    // float2 stores per channel (pp even -> 8B aligned).
    const float inv_nref = 1.0f / (float)NREF;
    #pragma unroll
    for (int c = 0; c < 3; c++) {
        float r0, r1;
        if (val0) r0 = acc[0][c] * inv_nref;
        else      r0 = __ldg(background + out_base + c*NPIX);
        if (val1) r1 = acc[1][c] * inv_nref;
        else      r1 = __ldg(background + out_base + c*NPIX + 1);
        *reinterpret_cast<float2*>(out + out_base + c*NPIX) = make_float2(r0, r1);
    }
}

extern "C" void kernel_launch(void* const* d_in, const int* in_sizes, int n_in,
                              void* d_out, int out_size) {
    const float* depth      = (const float*)d_in[0];
    const float* cam_K      = (const float*)d_in[1];
    const float* cam_W      = (const float*)d_in[2];
    const float* image_ref  = (const float*)d_in[3];
    const float* background = (const float*)d_in[4];
    const float* cube_diag  = (const float*)d_in[5];
    const float* cam_K_ref  = (const float*)d_in[6];
    const float* cam_W_ref  = (const float*)d_in[7];
    float* out = (float*)d_out;
    (void)cube_diag;  // divide-then-multiply round trip is an exact no-op path

    dim3 rgrid((IMG_STRIDE + TPB - 1) / TPB, NIMG);
    repack_kernel<<<rgrid, TPB>>>(image_ref);
    tex_kernel<<<NCAM*BLK_PER_IMG, TPB>>>(depth, background,
                                          cam_K, cam_W,
                                          cam_K_ref, cam_W_ref, out);
}

// round 14
// speedup vs baseline: 1.0199x; 1.0199x over previous
#include <cuda_runtime.h>
#include <cuda_fp16.h>

// Problem constants
#define BB    4
#define NR    2
#define NREF  4
#define HH    320
#define WW    320
#define NPIX  (HH*WW)
#define NCAM  (BB*NR)
#define NIMG  (BB*NREF)
#define TPB   256
#define PIX_PER_BLK (TPB*2)
#define BLK_PER_IMG (NPIX/PIX_PER_BLK)   // 200

// Zero-padded pair-packed fp16 RGBX reference images.
// Logical texel coords x in [-2, W], y in [-2, H+1]; texels outside
// [0,W-1]x[0,H-1] are zero. Entry (r, j) holds pair (texel[y][x], texel[y][x+1])
// with y = r-2, x = j-2. One LDG.128 fetches a bilinear corner row, and all
// out-of-range corners read zeros -> no masks or fixups needed in the sampler.
#define WP (WW + 3)              // 323 pair columns (x = -2 .. W)
#define HP (HH + 4)              // 324 rows         (y = -2 .. H+1)
#define IMG_STRIDE (WP * HP)     // 104652
__device__ uint4 g_pair[NIMG * IMG_STRIDE];   // ~26.8 MB

__device__ __forceinline__ void inv3(const float* m, float* o) {
    float a=m[0],b=m[1],c=m[2],d=m[3],e=m[4],f=m[5],g=m[6],h=m[7],i=m[8];
    float A  =  (e*i - f*h);
    float Bm = -(d*i - f*g);
    float C  =  (d*h - e*g);
    float det = a*A + b*Bm + c*C;
    float id = 1.0f/det;
    o[0]=A*id;              o[1]=-(b*i - c*h)*id;   o[2]= (b*f - c*e)*id;
    o[3]=Bm*id;             o[4]= (a*i - c*g)*id;   o[5]=-(a*f - c*d)*id;
    o[6]=C*id;              o[7]=-(a*h - b*g)*id;   o[8]= (a*e - b*d)*id;
}

__device__ __forceinline__ unsigned int ph2(float a, float b) {
    __half2 h = __floats2half2_rn(a, b);
    return *reinterpret_cast<const unsigned int*>(&h);
}
__device__ __forceinline__ float2 h2f2(unsigned int u) {
    return __half22float2(*reinterpret_cast<const __half2*>(&u));
}
__device__ __forceinline__ float h2lo(unsigned int u) {
    return __low2float(*reinterpret_cast<const __half2*>(&u));
}

// Planar CHW fp32 -> zero-padded pair-packed fp16 RGBX
// grid = (ceil(IMG_STRIDE/TPB), NIMG)
__global__ __launch_bounds__(TPB)
void repack_kernel(const float* __restrict__ src) {
    const int e = blockIdx.x * TPB + threadIdx.x;
    if (e >= IMG_STRIDE) return;
    const int img = blockIdx.y;
    const int r = e / WP;
    const int j = e - r * WP;
    const int y = r - 2;
    const int x = j - 2;

    float r0 = 0.f, g0 = 0.f, b0 = 0.f;
    float r1 = 0.f, g1 = 0.f, b1 = 0.f;
    if ((unsigned)y < (unsigned)HH) {
        const float* s = src + img * 3 * NPIX + y * WW;
        if ((unsigned)x < (unsigned)WW) {
            r0 = __ldg(s + x);
            g0 = __ldg(s + NPIX + x);
            b0 = __ldg(s + 2*NPIX + x);
        }
        const int x1 = x + 1;
        if ((unsigned)x1 < (unsigned)WW) {
            r1 = __ldg(s + x1);
            g1 = __ldg(s + NPIX + x1);
            b1 = __ldg(s + 2*NPIX + x1);
        }
    }
    uint4 q;
    q.x = ph2(r0, g0);
    q.y = ph2(b0, 0.0f);
    q.z = ph2(r1, g1);
    q.w = ph2(b1, 0.0f);
    g_pair[img * IMG_STRIDE + e] = q;
}

__global__ __launch_bounds__(TPB)
void tex_kernel(const float* __restrict__ depth,
                const float* __restrict__ background,
                const float* __restrict__ camK,
                const float* __restrict__ camW,
                const float* __restrict__ Kref,
                const float* __restrict__ Wref,
                float* __restrict__ out)
{
    const int cam = blockIdx.x / BLK_PER_IMG;            // b*NR + r
    const int pp  = (blockIdx.x % BLK_PER_IMG)*PIX_PER_BLK + threadIdx.x*2;
    const int b   = cam / NR;
    const int y   = pp / WW;
    const int x   = pp % WW;     // even; pixel pair is (x, x+1), same row

    // ---- Per-block fused camera constants in shared ----
    __shared__ float sP[NREF][9];
    __shared__ float sPt[NREF][3];
    __shared__ float sA[9];
    __shared__ float sBv[3];

    if (threadIdx.x < NREF) {
        const int v = threadIdx.x;
        float K[9], R[9], t[3];
        const float* kp = Kref + (b*NREF + v)*9;
        #pragma unroll
        for (int j = 0; j < 9; j++) K[j] = __ldg(kp + j);
        const float* w = Wref + (b*NREF + v)*12;
        #pragma unroll
        for (int r = 0; r < 3; r++) {
            R[r*3+0] = __ldg(w + r*4 + 0);
            R[r*3+1] = __ldg(w + r*4 + 1);
            R[r*3+2] = __ldg(w + r*4 + 2);
            t[r]     = __ldg(w + r*4 + 3);
        }
        #pragma unroll
        for (int r = 0; r < 3; r++) {
            #pragma unroll
            for (int c = 0; c < 3; c++)
                sP[v][r*3+c] = K[r*3+0]*R[0*3+c] + K[r*3+1]*R[1*3+c] + K[r*3+2]*R[2*3+c];
            sPt[v][r] = K[r*3+0]*t[0] + K[r*3+1]*t[1] + K[r*3+2]*t[2];
        }
    } else if (threadIdx.x == NREF) {
        float K[9], R[9], t[3], iK[9], iR[9];
        const float* kp = camK + cam*9;
        #pragma unroll
        for (int j = 0; j < 9; j++) K[j] = __ldg(kp + j);
        const float* w = camW + cam*12;
        #pragma unroll
        for (int r = 0; r < 3; r++) {
            R[r*3+0] = __ldg(w + r*4 + 0);
            R[r*3+1] = __ldg(w + r*4 + 1);
            R[r*3+2] = __ldg(w + r*4 + 2);
            t[r]     = __ldg(w + r*4 + 3);
        }
        inv3(K, iK);
        inv3(R, iR);
        #pragma unroll
        for (int r = 0; r < 3; r++) {
            #pragma unroll
            for (int c = 0; c < 3; c++)
                sA[r*3+c] = iR[r*3+0]*iK[0*3+c] + iR[r*3+1]*iK[1*3+c] + iR[r*3+2]*iK[2*3+c];
            sBv[r] = iR[r*3+0]*t[0] + iR[r*3+1]*t[1] + iR[r*3+2]*t[2];
        }
    }
    __syncthreads();

    const int out_base = cam*3*NPIX + pp;

    // Unconditional prefetches: depth pair + background pairs (overlap DRAM
    // latency with the gather phase). [R13 lesson: this prefetch > registers]
    const float2 d2  = *reinterpret_cast<const float2*>(depth + cam*NPIX + pp);
    const float2 bg0 = __ldg(reinterpret_cast<const float2*>(background + out_base));
    const float2 bg1 = __ldg(reinterpret_cast<const float2*>(background + out_base + NPIX));
    const float2 bg2 = __ldg(reinterpret_cast<const float2*>(background + out_base + 2*NPIX));

    const bool val0 = d2.x > 0.0f;
    const bool val1 = d2.y > 0.0f;
    const float yf = (float)y;

    // Backproject both pixels UNCONDITIONALLY (p3d = nd*(A@(x,y,1)) - Bv).
    // Invalid pixels (d=-1) produce deterministic garbage coordinates; the
    // sampler clamp keeps their loads in-bounds and the epilogue select
    // discards their accumulators. This keeps the gather loop branch-free.
    float p3[2][3];
    #pragma unroll
    for (int k = 0; k < 2; k++) {
        const float d  = (k == 0) ? d2.x : d2.y;
        const float xf = (float)(x + k);
        const float nd = -d;
        p3[k][0] = nd*(sA[0]*xf + sA[1]*yf + sA[2]) - sBv[0];
        p3[k][1] = nd*(sA[3]*xf + sA[4]*yf + sA[5]) - sBv[1];
        p3[k][2] = nd*(sA[6]*xf + sA[7]*yf + sA[8]) - sBv[2];
    }

    float acc[2][3] = {{0.f,0.f,0.f},{0.f,0.f,0.f}};

    if (val0 || val1) {
        #pragma unroll
        for (int v = 0; v < NREF; v++) {
            // Matrix in registers once per ref, shared by both pixels
            const float P0=sP[v][0], P1=sP[v][1], P2=sP[v][2];
            const float P3=sP[v][3], P4=sP[v][4], P5=sP[v][5];
            const float P6=sP[v][6], P7=sP[v][7], P8=sP[v][8];
            const float t0=sPt[v][0], t1=sPt[v][1], t2=sPt[v][2];
            const uint4* __restrict__ pimg = g_pair + (b*NREF + v) * IMG_STRIDE;

            #pragma unroll
            for (int k = 0; k < 2; k++) {
                const float px3 = p3[k][0], py3 = p3[k][1], pz3 = p3[k][2];
                const float qx = P0*px3 + P1*py3 + P2*pz3 + t0;
                const float qy = P3*px3 + P4*py3 + P5*pz3 + t1;
                const float qz = P6*px3 + P7*py3 + P8*pz3 + t2;
                const float iz = __fdividef(1.0f, qz);
                // Clamp into padded domain: everything outside lands on zero
                // texels (fmaxf/fminf also swallow NaN -> -2 -> zero region).
                const float px = fminf(fmaxf(qx * iz, -2.0f), (float)WW);
                const float py = fminf(fmaxf(qy * iz, -2.0f), (float)HH);

                const float x0 = floorf(px);
                const float y0 = floorf(py);
                const float wx = px - x0;
                const float wy = py - y0;
                const int ix = __float2int_rz(x0);   // [-2, W], exact
                const int iy = __float2int_rz(y0);   // [-2, H], exact

                const int idx = iy*WP + ix + (2*WP + 2);
                const uint4 top = __ldg(pimg + idx);
                const uint4 bot = __ldg(pimg + idx + WP);

                const float wx1 = wx,        wx0 = 1.0f - wx;
                const float wy1 = wy,        wy0 = 1.0f - wy;
                const float w00 = wx0*wy0, w01 = wx1*wy0;
                const float w10 = wx0*wy1, w11 = wx1*wy1;

                const float2 rg00 = h2f2(top.x); const float b00 = h2lo(top.y);
                const float2 rg01 = h2f2(top.z); const float b01 = h2lo(top.w);
                const float2 rg10 = h2f2(bot.x); const float b10 = h2lo(bot.y);
                const float2 rg11 = h2f2(bot.z); const float b11 = h2lo(bot.w);

                acc[k][0] += w00*rg00.x + w01*rg01.x + w10*rg10.x + w11*rg11.x;
                acc[k][1] += w00*rg00.y + w01*rg01.y + w10*rg10.y + w11*rg11.y;
                acc[k][2] += w00*b00    + w01*b01    + w10*b10    + w11*b11;
            }
        }
    }

    // Write output pairs (float2 per channel; pp even -> 8B aligned)
    const float inv_nref = 1.0f / (float)NREF;
    {
        float2 o0, o1, o2;
        o0.x = val0 ? acc[0][0]*inv_nref : bg0.x;
        o0.y = val1 ? acc[1][0]*inv_nref : bg0.y;
        o1.x = val0 ? acc[0][1]*inv_nref : bg1.x;
        o1.y = val1 ? acc[1][1]*inv_nref : bg1.y;
        o2.x = val0 ? acc[0][2]*inv_nref : bg2.x;
        o2.y = val1 ? acc[1][2]*inv_nref : bg2.y;
        *reinterpret_cast<float2*>(out + out_base)          = o0;
        *reinterpret_cast<float2*>(out + out_base + NPIX)   = o1;
        *reinterpret_cast<float2*>(out + out_base + 2*NPIX) = o2;
    }
}

extern "C" void kernel_launch(void* const* d_in, const int* in_sizes, int n_in,
                              void* d_out, int out_size) {
    const float* depth      = (const float*)d_in[0];
    const float* cam_K      = (const float*)d_in[1];
    const float* cam_W      = (const float*)d_in[2];
    const float* image_ref  = (const float*)d_in[3];
    const float* background = (const float*)d_in[4];
    const float* cube_diag  = (const float*)d_in[5];
    const float* cam_K_ref  = (const float*)d_in[6];
    const float* cam_W_ref  = (const float*)d_in[7];
    float* out = (float*)d_out;
    (void)cube_diag;  // divide-then-multiply round trip is an exact no-op path

    dim3 rgrid((IMG_STRIDE + TPB - 1) / TPB, NIMG);
    repack_kernel<<<rgrid, TPB>>>(image_ref);
    tex_kernel<<<NCAM*BLK_PER_IMG, TPB>>>(depth, background,
                                          cam_K, cam_W,
                                          cam_K_ref, cam_W_ref, out);
}